// round 1
// baseline (speedup 1.0000x reference)
#include <cuda_runtime.h>
#include <cstddef>

#define N_NODES 50000
#define DIM 64
#define EPS_C 1e-7f

// Scratch: per node, per dim, interleaved pair (sum_ex, sum_m_ex).
// Layout: g_scratch[node*128 + dim*2 + {0,1}], 16B-aligned for v4 red.
__device__ __align__(16) float g_scratch[(size_t)N_NODES * 2 * DIM];

// ---------------------------------------------------------------------------
// Pass 0: zero the scratch (graph-capturable, no memset API needed)
// ---------------------------------------------------------------------------
__global__ void zero_kernel() {
    size_t idx = (size_t)blockIdx.x * blockDim.x + threadIdx.x;
    size_t total = (size_t)N_NODES * 2 * DIM / 4;  // float4 count
    float4* p = reinterpret_cast<float4*>(g_scratch);
    if (idx < total) p[idx] = make_float4(0.f, 0.f, 0.f, 0.f);
}

// ---------------------------------------------------------------------------
// Pass 1: edge kernel. Two edges per warp (16 lanes each, 4 dims/lane).
// Computes m = relu(nf[src]+emb0[ef0]+emb1[ef1]) + eps, ex = exp(m*beta),
// and red-adds {ex, m*ex} pairs into g_scratch[dst].
// No max-subtraction needed: logits are small, exp is fp32-safe, and the
// resulting softmax is mathematically identical.
// ---------------------------------------------------------------------------
__global__ void edge_kernel(const float* __restrict__ nf,
                            const float* __restrict__ emb0,
                            const float* __restrict__ emb1,
                            const float* __restrict__ beta,
                            const int*   __restrict__ src,
                            const int*   __restrict__ dst,
                            const int*   __restrict__ ef0,
                            const int*   __restrict__ ef1,
                            int E) {
    __shared__ float4 s_e0[8 * 16];   // emb0: 8 rows x 64 = 128 float4
    __shared__ float4 s_e1[4 * 16];   // emb1: 4 rows x 64 = 64 float4
    int tid = threadIdx.x;
    if (tid < 128) s_e0[tid] = reinterpret_cast<const float4*>(emb0)[tid];
    if (tid < 64)  s_e1[tid] = reinterpret_cast<const float4*>(emb1)[tid];
    __syncthreads();

    const float B = beta[0];
    const int lane = tid & 31;
    const int half = lane >> 4;      // which of the 2 edges in this warp
    const int sub  = lane & 15;      // 16 lanes per edge, 4 dims each
    const int warp_id = blockIdx.x * (blockDim.x >> 5) + (tid >> 5);
    const int n_warps = gridDim.x * (blockDim.x >> 5);
    const int n_pairs = (E + 1) >> 1;

    for (int p = warp_id; p < n_pairs; p += n_warps) {
        int e = p * 2 + half;
        if (e >= E) continue;
        int s  = src[e];
        int d  = dst[e];
        int f0 = ef0[e];
        int f1 = ef1[e];

        float4 x  = reinterpret_cast<const float4*>(nf)[(size_t)s * 16 + sub];
        float4 a0 = s_e0[f0 * 16 + sub];
        float4 a1 = s_e1[f1 * 16 + sub];

        float m0 = fmaxf(x.x + a0.x + a1.x, 0.f) + EPS_C;
        float m1 = fmaxf(x.y + a0.y + a1.y, 0.f) + EPS_C;
        float m2 = fmaxf(x.z + a0.z + a1.z, 0.f) + EPS_C;
        float m3 = fmaxf(x.w + a0.w + a1.w, 0.f) + EPS_C;

        float ex0 = __expf(m0 * B);
        float ex1 = __expf(m1 * B);
        float ex2 = __expf(m2 * B);
        float ex3 = __expf(m3 * B);

        float* base = g_scratch + (size_t)d * (2 * DIM) + sub * 8;
        asm volatile("red.global.add.v4.f32 [%0], {%1,%2,%3,%4};"
                     :: "l"(base), "f"(ex0), "f"(m0 * ex0),
                        "f"(ex1), "f"(m1 * ex1) : "memory");
        asm volatile("red.global.add.v4.f32 [%0], {%1,%2,%3,%4};"
                     :: "l"(base + 4), "f"(ex2), "f"(m2 * ex2),
                        "f"(ex3), "f"(m3 * ex3) : "memory");
    }
}

// ---------------------------------------------------------------------------
// Pass 2: node kernel. Warp per node: msg = wsum/denom, MessageNorm,
// residual, then out = feats @ W + b with W in smem (shuffle-broadcast GEMM).
// ---------------------------------------------------------------------------
__global__ void node_kernel(const float* __restrict__ nf,
                            const float* __restrict__ W,
                            const float* __restrict__ b,
                            const float* __restrict__ scale,
                            float* __restrict__ out,
                            int N) {
    __shared__ float sW[DIM * DIM];   // 16 KB, row-major W[k][d]
    __shared__ float sb[DIM];
    for (int i = threadIdx.x; i < DIM * DIM; i += blockDim.x) sW[i] = W[i];
    if (threadIdx.x < DIM) sb[threadIdx.x] = b[threadIdx.x];
    __syncthreads();

    const float sc = scale[0];
    const int lane = threadIdx.x & 31;
    const int warp_id = blockIdx.x * (blockDim.x >> 5) + (threadIdx.x >> 5);
    const int n_warps = gridDim.x * (blockDim.x >> 5);

    for (int n = warp_id; n < N; n += n_warps) {
        // lane holds dims d0=2*lane, d1=2*lane+1
        float4 p = reinterpret_cast<const float4*>(g_scratch)[(size_t)n * 32 + lane];
        float msg0 = (p.x > 0.f) ? p.y / p.x : 0.f;
        float msg1 = (p.z > 0.f) ? p.w / p.z : 0.f;
        float2 x = reinterpret_cast<const float2*>(nf)[(size_t)n * 32 + lane];

        float smsg = msg0 * msg0 + msg1 * msg1;
        float snf  = x.x * x.x + x.y * x.y;
        #pragma unroll
        for (int o = 16; o; o >>= 1) {
            smsg += __shfl_xor_sync(0xFFFFFFFFu, smsg, o);
            snf  += __shfl_xor_sync(0xFFFFFFFFu, snf,  o);
        }
        // MessageNorm: msg_unit * ||nf|| * scale
        float coef = sqrtf(snf) * sc / fmaxf(sqrtf(smsg), 1e-12f);
        float f0 = x.x + msg0 * coef;
        float f1 = x.y + msg1 * coef;

        int d0 = lane * 2;
        float acc0 = sb[d0];
        float acc1 = sb[d0 + 1];
        #pragma unroll
        for (int k = 0; k < 32; k++) {
            float g0 = __shfl_sync(0xFFFFFFFFu, f0, k);   // feats[2k]
            float g1 = __shfl_sync(0xFFFFFFFFu, f1, k);   // feats[2k+1]
            float2 w0 = reinterpret_cast<const float2*>(sW)[(2 * k)     * 32 + lane];
            float2 w1 = reinterpret_cast<const float2*>(sW)[(2 * k + 1) * 32 + lane];
            acc0 += g0 * w0.x + g1 * w1.x;
            acc1 += g0 * w0.y + g1 * w1.y;
        }
        reinterpret_cast<float2*>(out)[(size_t)n * 32 + lane] = make_float2(acc0, acc1);
    }
}

// ---------------------------------------------------------------------------
extern "C" void kernel_launch(void* const* d_in, const int* in_sizes, int n_in,
                              void* d_out, int out_size) {
    const float* nf    = (const float*)d_in[0];
    const float* emb0  = (const float*)d_in[1];
    const float* emb1  = (const float*)d_in[2];
    const float* W     = (const float*)d_in[3];
    const float* b     = (const float*)d_in[4];
    const float* beta  = (const float*)d_in[5];
    const float* scale = (const float*)d_in[6];
    const int*   src   = (const int*)d_in[7];
    const int*   dst   = (const int*)d_in[8];
    const int*   ef0   = (const int*)d_in[9];
    const int*   ef1   = (const int*)d_in[10];

    const int E = in_sizes[7];
    const int N = in_sizes[0] / DIM;

    // Pass 0: zero scratch (1.6M float4)
    {
        int total = N_NODES * 2 * DIM / 4;
        int threads = 256;
        int blocks = (total + threads - 1) / threads;
        zero_kernel<<<blocks, threads>>>();
    }
    // Pass 1: edges (grid-stride, 2 edges/warp)
    edge_kernel<<<4736, 256>>>(nf, emb0, emb1, beta, src, dst, ef0, ef1, E);
    // Pass 2: nodes
    node_kernel<<<1184, 256>>>(nf, W, b, scale, (float*)d_out, N);
}